// round 15
// baseline (speedup 1.0000x reference)
#include <cuda_runtime.h>
#include <cuda_fp16.h>
#include <cstdint>
#include <math.h>

#define NMAX   25000
#define EMAX   400000
#define GMAX   1000
#define HID    185
#define INCH   9
#define LDAH   768      // padded concat width (4*192)
#define LDZ    192      // aggregated-activation row stride

// ---------------- scratch ----------------
__device__ int      g_cnt[NMAX];          // BSS zero; self-cleaned each call
__device__ int      g_bsum[128];
__device__ int      g_offs[NMAX + 1];
__device__ float    g_dis[NMAX];
__device__ int      g_erank[EMAX];
__device__ int      g_ready, g_done;      // scan barrier (self-resetting)
__device__ float    g_ax32[NMAX * INCH];  // fp32 x-aggregation accumulator
__device__ __align__(16) int2 g_csr[EMAX];   // (src, weight bits)
__device__ __align__(16) __half g_Axs[NMAX * LDAH];
__device__ __align__(16) __half g_Z[NMAX * LDZ];
__device__ __align__(16) __half g_W0th[192 * 16];
__device__ __align__(16) __half g_W0tl[192 * 16];
__device__ __align__(16) __half g_Whth[3 * 192 * 192];
__device__ __align__(16) __half g_Wjkth[192 * 768];
__device__ unsigned g_pool[GMAX * HID];
__device__ float    g_bnscale[4 * HID];
__device__ float    g_bnshift[4 * HID];

// ---------------- helpers ----------------
__device__ __forceinline__ unsigned enc_f(float f) {
    unsigned u = __float_as_uint(f);
    return (u & 0x80000000u) ? ~u : (u | 0x80000000u);
}
__device__ __forceinline__ float dec_f(unsigned e) {
    return (e & 0x80000000u) ? __uint_as_float(e & 0x7FFFFFFFu) : __uint_as_float(~e);
}
__device__ __forceinline__ void split_h(float v, __half& h, __half& l) {
    h = __float2half_rn(v);
    l = __float2half_rn(v - __half2float(h));
}
__device__ __forceinline__ uint32_t smem_u32(const void* p) {
    uint32_t a;
    asm("{ .reg .u64 t; cvta.to.shared.u64 t, %1; cvt.u32.u64 %0, t; }" : "=r"(a) : "l"(p));
    return a;
}
#define LDSM4(r0, r1, r2, r3, addr) \
    asm volatile("ldmatrix.sync.aligned.m8n8.x4.shared.b16 {%0,%1,%2,%3}, [%4];" \
        : "=r"(r0), "=r"(r1), "=r"(r2), "=r"(r3) : "r"(addr))
__device__ __forceinline__ void mma16(float* c, const uint32_t* a, const uint32_t* b) {
    asm volatile("mma.sync.aligned.m16n8k16.row.col.f32.f16.f16.f32 "
        "{%0,%1,%2,%3}, {%4,%5,%6,%7}, {%8,%9}, {%0,%1,%2,%3};"
        : "+f"(c[0]), "+f"(c[1]), "+f"(c[2]), "+f"(c[3])
        : "r"(a[0]), "r"(a[1]), "r"(a[2]), "r"(a[3]), "r"(b[0]), "r"(b[1]));
}
#define CP16(dst, src, sz) \
    asm volatile("cp.async.cg.shared.global [%0], [%1], 16, %2;" \
        :: "r"(dst), "l"(src), "r"(sz) : "memory")
#define CP_COMMIT() asm volatile("cp.async.commit_group;" ::: "memory")
#define CP_WAIT0()  asm volatile("cp.async.wait_group 0;" ::: "memory")
#define CP_WAIT1()  asm volatile("cp.async.wait_group 1;" ::: "memory")

// ---------------- merged: edge count+rank + weight prep + BN fold + pool init
__global__ void k_prep(const int* __restrict__ ei, int E, int EB,
                       const float* __restrict__ W0, const float* __restrict__ Wh,
                       const float* __restrict__ Wjk,
                       const float* __restrict__ gamma, const float* __restrict__ beta,
                       const float* __restrict__ mean, const float* __restrict__ var,
                       int G) {
    int t = threadIdx.x;
    if (blockIdx.x < EB) {
        int e = blockIdx.x * 256 + t;
        if (e < E) g_erank[e] = atomicAdd(&g_cnt[ei[E + e]], 1);
        return;
    }
    int b = blockIdx.x - EB;
    if (b < 12) {
        int idx = b * 256 + t;   // 192*16 = 3072
        int n = idx >> 4, k = idx & 15;
        float v = (n < HID && k < INCH) ? W0[k * HID + n] : 0.f;
        __half h, l; split_h(v, h, l);
        g_W0th[idx] = h; g_W0tl[idx] = l;
    } else if (b < 444) {
        int q = b - 12;
        int L = q / 144;
        int idx = (q - L * 144) * 256 + t;
        int n = idx / 192, k = idx % 192;
        float v = (n < HID && k < HID) ? Wh[(size_t)L * HID * HID + k * HID + n] : 0.f;
        g_Whth[L * 36864 + idx] = __float2half_rn(v);
    } else if (b < 1020) {
        int idx = (b - 444) * 256 + t;
        int n = idx / 768, k = idx % 768;
        int layer = k / 192, c = k % 192;
        float v = (n < HID && c < HID) ? Wjk[(size_t)(layer * HID + c) * HID + n] : 0.f;
        g_Wjkth[idx] = __float2half_rn(v);
    } else if (b < 1023) {
        int i = (b - 1020) * 256 + t;
        if (i < 4 * HID) {
            float sc = gamma[i] * rsqrtf(var[i] + 1e-5f);
            g_bnscale[i] = sc;
            g_bnshift[i] = beta[i] - mean[i] * sc;
        }
    } else {
        int i = (b - 1023) * 256 + t;
        if (i < G * HID) g_pool[i] = 0x007FFFFFu;    // enc(-inf)
    }
}

// single-launch scan (SB <= 128 blocks, all resident -> spin barrier safe)
__global__ void k_scan(int N, int SB) {
    __shared__ int sh[256];
    int t = threadIdx.x, b = blockIdx.x;
    int i = b * 256 + t;
    int v = (i < N) ? g_cnt[i] : 0;
    sh[t] = v;
    __syncthreads();
    for (int o = 1; o < 256; o <<= 1) {
        int a = (t >= o) ? sh[t - o] : 0;
        __syncthreads();
        sh[t] += a;
        __syncthreads();
    }
    int part = sh[t] - v;
    if (t == 255) {
        g_bsum[b] = sh[255];
        __threadfence();
    }
    __syncthreads();
    if (t == 0) {
        atomicAdd(&g_ready, 1);
        while (atomicAdd(&g_ready, 0) < SB) __nanosleep(32);
    }
    __syncthreads();
    if (t < 128) sh[t] = (t < SB) ? g_bsum[t] : 0;
    __syncthreads();
    for (int o = 1; o < 128; o <<= 1) {
        int a = (t >= o && t < 128) ? sh[t - o] : 0;
        __syncthreads();
        if (t < 128) sh[t] += a;
        __syncthreads();
    }
    int pre = sh[b] - g_bsum[b];
    if (i < N) {
        int off = part + pre;
        int c = g_cnt[i];
        g_cnt[i] = 0;
        g_offs[i] = off;
        if (i == N - 1) g_offs[N] = off + c;
        g_dis[i] = rsqrtf((float)c + 1.0f);
#pragma unroll
        for (int cc = 0; cc < INCH; cc++) g_ax32[i * INCH + cc] = 0.f;
    }
    __syncthreads();
    if (t == 0) {
        int d = atomicAdd(&g_done, 1) + 1;
        if (d == SB) { g_done = 0; g_ready = 0; __threadfence(); }
    }
}

// fill CSR (atomic-free) + scatter layer-0 x aggregation
__global__ void k_fill(const int* __restrict__ ei, const float* __restrict__ x, int E) {
    int e = blockIdx.x * blockDim.x + threadIdx.x;
    if (e >= E) return;
    int s = ei[e], d = ei[E + e];
    float ws = g_dis[s];
    g_csr[g_offs[d] + g_erank[e]] = make_int2(s, __float_as_int(ws));
    float* dst = &g_ax32[d * INCH];
    const float* xs = &x[s * INCH];
#pragma unroll
    for (int c = 0; c < INCH; c++) atomicAdd(&dst[c], ws * xs[c]);
}

// ---------------- fp16 GEMM: CTA tile 128x64, 3 CTAs/SM ----------------------
// stage (bytes): sA 0 (128x144 = 18432), sB 18432 (64x144 = 9216); kw16 lo at +32
#define STG 27648
#define SMEM_BYTES (2 * STG)
#define SBH_OFF 18432u
#define B_LO_KW16 32u

__device__ __forceinline__ void ld_stage(
    uint32_t smb,
    const __half* __restrict__ A, int lda,
    const __half* __restrict__ Bh, const __half* __restrict__ Bl, int ldb,
    int rowBase, int colBase, int k0, int Nrows, int tid, int dual, int kw16) {
    if (kw16) {
        // B only (A computed in-register): 64 rows x 16 halves; lo packed at +32
        if (tid < 128) {
            int n = tid >> 1, jb = tid & 1;
            size_t go = (size_t)(colBase + n) * ldb + jb * 8;
            uint32_t d = smb + SBH_OFF + n * 144 + jb * 16;
            CP16(d, Bh + go, 16);
            if (dual) CP16(d + B_LO_KW16, Bl + go, 16);
        }
        return;
    }
    // A: 128 rows x 64 halves = 1024 chunks -> 4 iters
#pragma unroll
    for (int s = 0; s < 4; s++) {
        int idx = tid + s * 256;
        int r = idx >> 3, j = idx & 7;
        int gr = rowBase + r;
        int sz = (gr < Nrows) ? 16 : 0;
        int grc = min(gr, Nrows - 1);
        size_t go = (size_t)grc * lda + k0 + j * 8;
        CP16(smb + r * 144 + j * 16, A + go, sz);
    }
    // B: 64 rows x 64 halves = 512 chunks -> 2 iters
#pragma unroll
    for (int s = 0; s < 2; s++) {
        int idx = tid + s * 256;
        int n = idx >> 3, j = idx & 7;
        size_t go = (size_t)(colBase + n) * ldb + k0 + j * 8;
        CP16(smb + SBH_OFF + n * 144 + j * 16, Bh + go, 16);
    }
}

// 8 warps: wm = w&3 (32-row groups), wn = w>>2 (32-col groups); warp tile 32x32
// mode 2: bias+bn+relu -> fp16 half2    mode 3: bias -> smem-staged max-pool
// kw16: layer-0 — A tile computed in-register from g_ax32 + xin, dual B packed
__global__ void __launch_bounds__(256, 3)
k_mma(const __half* __restrict__ A, int lda,
      const __half* __restrict__ Bh, const __half* __restrict__ Bl, int ldb,
      int Nrows, int Ktiles,
      __half* __restrict__ O,
      const float* __restrict__ bias, const float* __restrict__ scale,
      const float* __restrict__ shift,
      const int* __restrict__ batch, unsigned* __restrict__ pool,
      int mode, int dual, int ksteps, int kw16,
      const float* __restrict__ xin) {
    extern __shared__ __align__(16) char smch[];
    uint32_t sb = smem_u32(smch);

    int tid = threadIdx.x, lane = tid & 31, w = tid >> 5;
    int wm = w & 3, wn = w >> 2;
    int rowBase = blockIdx.y * 128, colBase = blockIdx.x * 64;

    float acc[2][4][4];
#pragma unroll
    for (int i = 0; i < 2; i++)
#pragma unroll
        for (int j = 0; j < 4; j++)
#pragma unroll
            for (int q = 0; q < 4; q++) acc[i][j][q] = 0.f;

    const uint32_t offA = (uint32_t)((wm * 32 + (lane & 15)) * 72 + (lane >> 4) * 8) << 1;
    const uint32_t offB = SBH_OFF +
        ((uint32_t)((wn * 32 + (lane & 7) + ((lane >> 4) << 3)) * 72 + ((lane >> 3) & 1) * 8) << 1);
    const uint32_t MF = 2304;   // 16 rows * 144 B

    ld_stage(sb, A, lda, Bh, Bl, ldb, rowBase, colBase, 0, Nrows, tid, dual, kw16);
    CP_COMMIT();

    if (kw16 && tid < 128) {
        // layer-0 A row in-register: dn*ax + dn^2*x, fp32 -> fp16
        int gr = rowBase + tid;
        __align__(16) __half hv[16];
#pragma unroll
        for (int c = 0; c < 16; c++) hv[c] = __float2half_rn(0.f);
        if (gr < Nrows) {
            float dn = g_dis[gr];
            float dn2 = dn * dn;
#pragma unroll
            for (int c = 0; c < INCH; c++) {
                float v = dn * g_ax32[gr * INCH + c] + dn2 * xin[gr * INCH + c];
                hv[c] = __float2half_rn(v);
            }
        }
        *(uint4*)(smch + tid * 144)      = *(uint4*)&hv[0];
        *(uint4*)(smch + tid * 144 + 16) = *(uint4*)&hv[8];
    }

    for (int kt = 0; kt < Ktiles; kt++) {
        uint32_t stb = sb + (uint32_t)(kt & 1) * STG;
        if (kt + 1 < Ktiles) {
            ld_stage(sb + (uint32_t)((kt + 1) & 1) * STG, A, lda, Bh, Bl, ldb,
                     rowBase, colBase, (kt + 1) * 64, Nrows, tid, dual, kw16);
            CP_COMMIT();
            CP_WAIT1();
        } else {
            CP_WAIT0();
        }
        __syncthreads();

        uint32_t aA = stb + offA;
        uint32_t aB = stb + offB;
        for (int ks = 0; ks < ksteps; ks++) {
            uint32_t kso = ks * 32;
            uint32_t bh[4][2], bl[4][2];
            LDSM4(bh[0][0], bh[0][1], bh[1][0], bh[1][1], aB + kso);
            LDSM4(bh[2][0], bh[2][1], bh[3][0], bh[3][1], aB + MF + kso);
            if (dual) {
                LDSM4(bl[0][0], bl[0][1], bl[1][0], bl[1][1], aB + B_LO_KW16 + kso);
                LDSM4(bl[2][0], bl[2][1], bl[3][0], bl[3][1], aB + B_LO_KW16 + MF + kso);
            }
#pragma unroll
            for (int mf = 0; mf < 2; mf++) {
                uint32_t ar[4];
                LDSM4(ar[0], ar[1], ar[2], ar[3], aA + mf * MF + kso);
#pragma unroll
                for (int nf = 0; nf < 4; nf++) {
                    mma16(acc[mf][nf], ar, bh[nf]);
                    if (dual) mma16(acc[mf][nf], ar, bl[nf]);
                }
            }
        }
        __syncthreads();
    }

    int gid = lane >> 2, tig = lane & 3;
    if (mode == 2) {
#pragma unroll
        for (int mf = 0; mf < 2; mf++) {
#pragma unroll
            for (int half = 0; half < 2; half++) {
                int r = rowBase + wm * 32 + mf * 16 + gid + half * 8;
                if (r >= Nrows) continue;
#pragma unroll
                for (int nf = 0; nf < 4; nf++) {
                    int c0 = colBase + wn * 32 + nf * 8 + tig * 2;
                    float v0 = acc[mf][nf][half * 2];
                    float v1 = acc[mf][nf][half * 2 + 1];
                    float o0 = 0.f, o1 = 0.f;
                    if (c0 < HID)
                        o0 = fmaxf(fmaf(v0 + bias[c0], scale[c0], shift[c0]), 0.f);
                    if (c0 + 1 < HID)
                        o1 = fmaxf(fmaf(v1 + bias[c0 + 1], scale[c0 + 1], shift[c0 + 1]), 0.f);
                    *(__half2*)(O + (size_t)r * LDAH + c0) =
                        __halves2half2(__float2half_rn(o0), __float2half_rn(o1));
                }
            }
        }
    } else {
        // mode 3: smem-staged max-pool (batch sorted; 128-row tile spans <= 128 graphs)
        unsigned* spool = (unsigned*)smch;
        int g0 = batch[rowBase];
        int rlast = min(rowBase + 127, Nrows - 1);
        int range = batch[rlast] - g0 + 1;
        for (int i = tid; i < range * 64; i += 256) spool[i] = 0x007FFFFFu;
        __syncthreads();
#pragma unroll
        for (int mf = 0; mf < 2; mf++) {
#pragma unroll
            for (int half = 0; half < 2; half++) {
                int r = rowBase + wm * 32 + mf * 16 + gid + half * 8;
                if (r >= Nrows) continue;
                int bloc = (batch[r] - g0) * 64;
#pragma unroll
                for (int nf = 0; nf < 4; nf++) {
                    int c0 = colBase + wn * 32 + nf * 8 + tig * 2;
                    float v0 = acc[mf][nf][half * 2];
                    float v1 = acc[mf][nf][half * 2 + 1];
                    int cl = wn * 32 + nf * 8 + tig * 2;
                    if (c0 < HID)
                        atomicMax(&spool[bloc + cl], enc_f(v0 + bias[c0]));
                    if (c0 + 1 < HID)
                        atomicMax(&spool[bloc + cl + 1], enc_f(v1 + bias[c0 + 1]));
                }
            }
        }
        __syncthreads();
        for (int i = tid; i < range * 64; i += 256) {
            int bgr = i >> 6;
            int c = colBase + (i & 63);
            if (c < HID)
                atomicMax(&pool[(g0 + bgr) * HID + c], spool[i]);
        }
    }
}

// fp16 aggregation: 2 nodes/block, thread owns 4 channels (8B gathers)
__global__ void k_agg16(const __half* __restrict__ src, int N) {
    int t = threadIdx.x;           // 0..95
    int g = t / 48, lt = t - g * 48;
    int n = blockIdx.x * 2 + g;
    if (n >= N) return;
    int c0 = lt * 4;               // 0..188
    int s0 = g_offs[n], s1 = g_offs[n + 1];
    float a0 = 0.f, a1 = 0.f, a2 = 0.f, a3 = 0.f;
    int e = s0;
    for (; e + 2 <= s1; e += 2) {
        int2 e0 = g_csr[e], e1 = g_csr[e + 1];
        uint2 p0 = *(const uint2*)(src + (size_t)e0.x * LDAH + c0);
        uint2 p1 = *(const uint2*)(src + (size_t)e1.x * LDAH + c0);
        float w0 = __int_as_float(e0.y), w1 = __int_as_float(e1.y);
        float2 q0 = __half22float2(*(__half2*)&p0.x);
        float2 q1 = __half22float2(*(__half2*)&p0.y);
        float2 r0 = __half22float2(*(__half2*)&p1.x);
        float2 r1 = __half22float2(*(__half2*)&p1.y);
        a0 += w0 * q0.x + w1 * r0.x;
        a1 += w0 * q0.y + w1 * r0.y;
        a2 += w0 * q1.x + w1 * r1.x;
        a3 += w0 * q1.y + w1 * r1.y;
    }
    if (e < s1) {
        int2 ed = g_csr[e];
        uint2 p = *(const uint2*)(src + (size_t)ed.x * LDAH + c0);
        float w = __int_as_float(ed.y);
        float2 q0 = __half22float2(*(__half2*)&p.x);
        float2 q1 = __half22float2(*(__half2*)&p.y);
        a0 += w * q0.x; a1 += w * q0.y; a2 += w * q1.x; a3 += w * q1.y;
    }
    float dn = g_dis[n], dn2 = dn * dn;
    uint2 ps = *(const uint2*)(src + (size_t)n * LDAH + c0);
    float2 s0f = __half22float2(*(__half2*)&ps.x);
    float2 s1f = __half22float2(*(__half2*)&ps.y);
    float v0 = dn * a0 + dn2 * s0f.x;
    float v1 = dn * a1 + dn2 * s0f.y;
    float v2 = dn * a2 + dn2 * s1f.x;
    float v3 = dn * a3 + dn2 * s1f.y;
    uint2 out;
    *(__half2*)&out.x = __floats2half2_rn(v0, v1);
    *(__half2*)&out.y = __floats2half2_rn(v2, v3);
    *(uint2*)(g_Z + (size_t)n * LDZ + c0) = out;
}

__global__ void k_finalize(const float* __restrict__ Wout,
                           const float* __restrict__ bout,
                           float* __restrict__ out, int G) {
    int g = blockIdx.x, t = threadIdx.x;
    __shared__ float red[256];
    float p = 0.f;
    for (int c = t; c < HID; c += 256)
        p += dec_f(g_pool[g * HID + c]) * Wout[c];
    red[t] = p;
    __syncthreads();
    for (int o = 128; o; o >>= 1) {
        if (t < o) red[t] += red[t + o];
        __syncthreads();
    }
    if (t == 0) out[g] = red[0] + bout[0];
}

// ---------------- host launcher ----------------
extern "C" void kernel_launch(void* const* d_in, const int* in_sizes, int n_in,
                              void* d_out, int out_size) {
    const float* x     = (const float*)d_in[0];
    const int*   ei    = (const int*)  d_in[1];
    const int*   batch = (const int*)  d_in[2];
    const float* W0    = (const float*)d_in[3];
    const float* b0    = (const float*)d_in[4];
    const float* W_h   = (const float*)d_in[5];
    const float* b_h   = (const float*)d_in[6];
    const float* bn_g  = (const float*)d_in[7];
    const float* bn_b  = (const float*)d_in[8];
    const float* bn_m  = (const float*)d_in[9];
    const float* bn_v  = (const float*)d_in[10];
    const float* W_jk  = (const float*)d_in[11];
    const float* b_jk  = (const float*)d_in[12];
    const float* W_out = (const float*)d_in[13];
    const float* b_out = (const float*)d_in[14];
    float* out = (float*)d_out;

    int N = in_sizes[0] / INCH;
    int E = in_sizes[1] / 2;
    int G = out_size;
    int SB = (N + 255) / 256;
    int EB = (E + 255) / 256;
    int poolBlks = (G * HID + 255) / 256;

    cudaFuncSetAttribute(k_mma, cudaFuncAttributeMaxDynamicSharedMemorySize, SMEM_BYTES);

    __half *axs, *zz, *w0h, *w0l, *whh, *wjh;
    cudaGetSymbolAddress((void**)&axs, g_Axs);
    cudaGetSymbolAddress((void**)&zz,  g_Z);
    cudaGetSymbolAddress((void**)&w0h, g_W0th);
    cudaGetSymbolAddress((void**)&w0l, g_W0tl);
    cudaGetSymbolAddress((void**)&whh, g_Whth);
    cudaGetSymbolAddress((void**)&wjh, g_Wjkth);
    float *bns, *bnh;
    cudaGetSymbolAddress((void**)&bns, g_bnscale);
    cudaGetSymbolAddress((void**)&bnh, g_bnshift);
    unsigned* pool;
    cudaGetSymbolAddress((void**)&pool, g_pool);

    k_prep<<<EB + 1023 + poolBlks, 256>>>(ei, E, EB, W0, W_h, W_jk,
                                          bn_g, bn_b, bn_m, bn_v, G);
    k_scan<<<SB, 256>>>(N, SB);
    k_fill<<<(E + 255) / 256, 256>>>(ei, x, E);

    dim3 grid(3, (N + 127) / 128);   // 588 CTAs @ 3 CTAs/SM

    // layer 0: A computed in-register; dual W0 (lo packed in B rows)
    k_mma<<<grid, 256, SMEM_BYTES>>>((const __half*)0, 0, w0h, w0l, 16, N, 1,
                                     axs, b0, bns, bnh,
                                     (const int*)0, (unsigned*)0, 2, 1, 1, 1, x);
    // hidden layers 1..3: aggregate fp16 activations, then GEMM (single fp16 weights)
    for (int i = 1; i <= 3; i++) {
        k_agg16<<<(N + 1) / 2, 96>>>(axs + (size_t)(i - 1) * 192, N);
        k_mma<<<grid, 256, SMEM_BYTES>>>(zz, LDZ,
                                         whh + (size_t)(i - 1) * 36864,
                                         whh + (size_t)(i - 1) * 36864, 192,
                                         N, 3,
                                         axs + (size_t)i * 192,
                                         b_h + (size_t)(i - 1) * HID,
                                         bns + i * HID, bnh + i * HID,
                                         (const int*)0, (unsigned*)0, 2, 0, 4, 0,
                                         (const float*)0);
    }
    // JK GEMM fused with smem-staged max-pool (single fp16 weights)
    k_mma<<<grid, 256, SMEM_BYTES>>>(axs, LDAH, wjh, wjh, 768, N, 12,
                                     (__half*)0,
                                     b_jk, (const float*)0, (const float*)0,
                                     batch, pool, 3, 0, 4, 0, (const float*)0);

    k_finalize<<<G, 256>>>(W_out, b_out, out, G);
}

// round 16
// speedup vs baseline: 1.0204x; 1.0204x over previous
#include <cuda_runtime.h>
#include <cuda_fp16.h>
#include <cstdint>
#include <math.h>

#define NMAX   25000
#define EMAX   400000
#define GMAX   1000
#define HID    185
#define INCH   9
#define LDAH   768      // padded concat width (4*192)
#define LDZ    192      // aggregated-activation row stride

// ---------------- scratch ----------------
__device__ int      g_cnt[NMAX];          // BSS zero; self-cleaned each call
__device__ int      g_part[NMAX];
__device__ int      g_bsum[128];
__device__ int      g_offs[NMAX + 1];
__device__ float    g_dis[NMAX];
__device__ int      g_erank[EMAX];
__device__ __align__(16) int2 g_csr[EMAX];   // (src, weight bits)
__device__ __align__(16) __half g_A0[NMAX * 16];
__device__ __align__(16) __half g_Axs[NMAX * LDAH];
__device__ __align__(16) __half g_Z[NMAX * LDZ];
__device__ __align__(16) __half g_W0th[192 * 16];
__device__ __align__(16) __half g_W0tl[192 * 16];
__device__ __align__(16) __half g_Whth[3 * 192 * 192];
__device__ __align__(16) __half g_Wjkth[192 * 768];
__device__ unsigned g_pool[GMAX * HID];
__device__ float    g_bnscale[4 * HID];
__device__ float    g_bnshift[4 * HID];

// ---------------- helpers ----------------
__device__ __forceinline__ unsigned enc_f(float f) {
    unsigned u = __float_as_uint(f);
    return (u & 0x80000000u) ? ~u : (u | 0x80000000u);
}
__device__ __forceinline__ float dec_f(unsigned e) {
    return (e & 0x80000000u) ? __uint_as_float(e & 0x7FFFFFFFu) : __uint_as_float(~e);
}
__device__ __forceinline__ void split_h(float v, __half& h, __half& l) {
    h = __float2half_rn(v);
    l = __float2half_rn(v - __half2float(h));
}
__device__ __forceinline__ uint32_t smem_u32(const void* p) {
    uint32_t a;
    asm("{ .reg .u64 t; cvta.to.shared.u64 t, %1; cvt.u32.u64 %0, t; }" : "=r"(a) : "l"(p));
    return a;
}
#define LDSM4(r0, r1, r2, r3, addr) \
    asm volatile("ldmatrix.sync.aligned.m8n8.x4.shared.b16 {%0,%1,%2,%3}, [%4];" \
        : "=r"(r0), "=r"(r1), "=r"(r2), "=r"(r3) : "r"(addr))
__device__ __forceinline__ void mma16(float* c, const uint32_t* a, const uint32_t* b) {
    asm volatile("mma.sync.aligned.m16n8k16.row.col.f32.f16.f16.f32 "
        "{%0,%1,%2,%3}, {%4,%5,%6,%7}, {%8,%9}, {%0,%1,%2,%3};"
        : "+f"(c[0]), "+f"(c[1]), "+f"(c[2]), "+f"(c[3])
        : "r"(a[0]), "r"(a[1]), "r"(a[2]), "r"(a[3]), "r"(b[0]), "r"(b[1]));
}
#define CP16(dst, src, sz) \
    asm volatile("cp.async.cg.shared.global [%0], [%1], 16, %2;" \
        :: "r"(dst), "l"(src), "r"(sz) : "memory")
#define CP_COMMIT() asm volatile("cp.async.commit_group;" ::: "memory")
#define CP_WAIT0()  asm volatile("cp.async.wait_group 0;" ::: "memory")
#define CP_WAIT1()  asm volatile("cp.async.wait_group 1;" ::: "memory")

// ---------------- merged: edge count+rank + weight prep + BN fold + pool init
__global__ void k_prep(const int* __restrict__ ei, int E, int EB,
                       const float* __restrict__ W0, const float* __restrict__ Wh,
                       const float* __restrict__ Wjk,
                       const float* __restrict__ gamma, const float* __restrict__ beta,
                       const float* __restrict__ mean, const float* __restrict__ var,
                       int G) {
    int t = threadIdx.x;
    if (blockIdx.x < EB) {
        int e = blockIdx.x * 256 + t;
        if (e < E) g_erank[e] = atomicAdd(&g_cnt[ei[E + e]], 1);
        return;
    }
    int b = blockIdx.x - EB;
    if (b < 12) {
        int idx = b * 256 + t;   // 192*16 = 3072
        int n = idx >> 4, k = idx & 15;
        float v = (n < HID && k < INCH) ? W0[k * HID + n] : 0.f;
        __half h, l; split_h(v, h, l);
        g_W0th[idx] = h; g_W0tl[idx] = l;
    } else if (b < 444) {
        int q = b - 12;
        int L = q / 144;
        int idx = (q - L * 144) * 256 + t;
        int n = idx / 192, k = idx % 192;
        float v = (n < HID && k < HID) ? Wh[(size_t)L * HID * HID + k * HID + n] : 0.f;
        g_Whth[L * 36864 + idx] = __float2half_rn(v);
    } else if (b < 1020) {
        int idx = (b - 444) * 256 + t;
        int n = idx / 768, k = idx % 768;
        int layer = k / 192, c = k % 192;
        float v = (n < HID && c < HID) ? Wjk[(size_t)(layer * HID + c) * HID + n] : 0.f;
        g_Wjkth[idx] = __float2half_rn(v);
    } else if (b < 1023) {
        int i = (b - 1020) * 256 + t;
        if (i < 4 * HID) {
            float sc = gamma[i] * rsqrtf(var[i] + 1e-5f);
            g_bnscale[i] = sc;
            g_bnshift[i] = beta[i] - mean[i] * sc;
        }
    } else {
        int i = (b - 1023) * 256 + t;
        if (i < G * HID) g_pool[i] = 0x007FFFFFu;    // enc(-inf)
    }
}

__global__ void k_scan_blk(int N) {
    __shared__ int sh[256];
    int i = blockIdx.x * 256 + threadIdx.x;
    int v = (i < N) ? g_cnt[i] : 0;
    sh[threadIdx.x] = v;
    __syncthreads();
    for (int o = 1; o < 256; o <<= 1) {
        int a = (threadIdx.x >= o) ? sh[threadIdx.x - o] : 0;
        __syncthreads();
        sh[threadIdx.x] += a;
        __syncthreads();
    }
    if (i < N) g_part[i] = sh[threadIdx.x] - v;
    if (threadIdx.x == 255) g_bsum[blockIdx.x] = sh[255];
}
__global__ void k_scan_add(int N, int SB) {
    __shared__ int sh[128];
    int t = threadIdx.x;
    if (t < 128) sh[t] = (t < SB) ? g_bsum[t] : 0;
    __syncthreads();
    for (int o = 1; o < 128; o <<= 1) {
        int a = (t >= o && t < 128) ? sh[t - o] : 0;
        __syncthreads();
        if (t < 128) sh[t] += a;
        __syncthreads();
    }
    int i = blockIdx.x * 256 + t;
    if (i >= N) return;
    int pre = sh[blockIdx.x] - g_bsum[blockIdx.x];
    int off = g_part[i] + pre;
    int c = g_cnt[i];
    g_cnt[i] = 0;
    g_offs[i] = off;
    if (i == N - 1) g_offs[N] = off + c;
    g_dis[i] = rsqrtf((float)c + 1.0f);
}
// atomic-free fill: slot = offs[dst] + precomputed rank
__global__ void k_fill(const int* __restrict__ ei, int E) {
    int e = blockIdx.x * blockDim.x + threadIdx.x;
    if (e >= E) return;
    int s = ei[e], d = ei[E + e];
    int p = g_offs[d] + g_erank[e];
    g_csr[p] = make_int2(s, __float_as_int(g_dis[s]));
}

// aggregate raw x (9 ch) -> fp16 A0 [N x 16]
__global__ void k_aggregate_x(const float* __restrict__ x, int N) {
    int warp = (blockIdx.x * blockDim.x + threadIdx.x) >> 5;
    int lane = threadIdx.x & 31;
    if (warp >= N) return;
    int n = warp;
    int s0 = g_offs[n], s1 = g_offs[n + 1];
    float acc[INCH];
#pragma unroll
    for (int c = 0; c < INCH; c++) acc[c] = 0.f;
    for (int e = s0 + lane; e < s1; e += 32) {
        int2 ed = g_csr[e];
        float w = __int_as_float(ed.y);
#pragma unroll
        for (int c = 0; c < INCH; c++) acc[c] += w * x[ed.x * INCH + c];
    }
#pragma unroll
    for (int c = 0; c < INCH; c++)
#pragma unroll
        for (int o = 16; o; o >>= 1)
            acc[c] += __shfl_xor_sync(0xffffffffu, acc[c], o);
    if (lane == 0) {
        float dn = g_dis[n];
#pragma unroll
        for (int c = 0; c < INCH; c++) {
            float v = dn * acc[c] + dn * dn * x[n * INCH + c];
            g_A0[n * 16 + c] = __float2half_rn(v);
        }
    }
    if (lane < 16 - INCH)
        g_A0[n * 16 + INCH + lane] = __float2half_rn(0.f);
}

// ---------------- fp16 GEMM: CTA tile 256x64, single-wave grid ---------------
// stage (bytes): sA 0 (256x144 = 36864), sBh 36864 (9216), sBl 46080 (9216)
#define STG 55296
#define SMEM_BYTES (2 * STG)
#define SBH_OFF 36864u
#define SBL_DELTA 9216u

// strength-reduced stage loader: decompose tid once, advance by constant strides
__device__ __forceinline__ void ld_stage(
    uint32_t smb,
    const __half* __restrict__ A, int lda,
    const __half* __restrict__ Bh, const __half* __restrict__ Bl, int ldb,
    int rowBase, int colBase, int k0, int Nrows, int tid, int dual, int kw16) {
    int r = tid >> 3, j = tid & 7;            // r in 0..31
    if (kw16) {
        // A: 256 rows x 16 halves (2 chunks/row); thread -> (row = tid>>1, chunk = tid&1)
        int r2 = tid >> 1, j2 = tid & 1;
        uint32_t d = smb + r2 * 144 + j2 * 16;
        size_t go = (size_t)(rowBase + r2) * lda + j2 * 8;
        size_t step = (size_t)128 * lda;
#pragma unroll
        for (int s = 0; s < 2; s++) {
            int gr = rowBase + r2 + s * 128;
            CP16(d, A + ((gr < Nrows) ? go : 0), (gr < Nrows) ? 16 : 0);
            d += 128 * 144;
            go += step;
        }
        // B: 64 rows x 16 halves
        if (tid < 128) {
            int n = tid >> 1, jb = tid & 1;
            size_t gob = (size_t)(colBase + n) * ldb + jb * 8;
            uint32_t db = smb + SBH_OFF + n * 144 + jb * 16;
            CP16(db, Bh + gob, 16);
            if (dual) CP16(db + SBL_DELTA, Bl + gob, 16);
        }
        return;
    }
    // A: 256 rows x 64 halves; thread base (r, j), 8 iters stepping 32 rows
    {
        uint32_t d = smb + r * 144 + j * 16;
        size_t go = (size_t)(rowBase + r) * lda + k0 + j * 8;
        size_t step = (size_t)32 * lda;
#pragma unroll
        for (int s = 0; s < 8; s++) {
            int gr = rowBase + r + s * 32;
            CP16(d, A + ((gr < Nrows) ? go : 0), (gr < Nrows) ? 16 : 0);
            d += 32 * 144;
            go += step;
        }
    }
    // B: 64 rows x 64 halves; 2 iters stepping 32 rows (always in-bounds, padded)
    {
        uint32_t db = smb + SBH_OFF + r * 144 + j * 16;
        size_t gob = (size_t)(colBase + r) * ldb + k0 + j * 8;
        size_t stepb = (size_t)32 * ldb;
#pragma unroll
        for (int s = 0; s < 2; s++) {
            CP16(db, Bh + gob, 16);
            if (dual) CP16(db + SBL_DELTA, Bl + gob, 16);
            db += 32 * 144;
            gob += stepb;
        }
    }
}

// warp layout: 8 warps, wm = w&3 (64-row groups), wn = w>>2 (32-col groups)
// mode 2: bias+bn+relu -> fp16 half2    mode 3: bias -> smem-staged max-pool
__global__ void __launch_bounds__(256, 2)
k_mma(const __half* __restrict__ A, int lda,
      const __half* __restrict__ Bh, const __half* __restrict__ Bl, int ldb,
      int Nrows, int Ktiles,
      __half* __restrict__ O,
      const float* __restrict__ bias, const float* __restrict__ scale,
      const float* __restrict__ shift,
      const int* __restrict__ batch, unsigned* __restrict__ pool,
      int mode, int dual, int ksteps, int kw16) {
    extern __shared__ __align__(16) char smch[];
    uint32_t sb = smem_u32(smch);

    int tid = threadIdx.x, lane = tid & 31, w = tid >> 5;
    int wm = w & 3, wn = w >> 2;
    int rowBase = blockIdx.y * 256, colBase = blockIdx.x * 64;

    float acc[4][4][4];
#pragma unroll
    for (int i = 0; i < 4; i++)
#pragma unroll
        for (int j = 0; j < 4; j++)
#pragma unroll
            for (int q = 0; q < 4; q++) acc[i][j][q] = 0.f;

    const uint32_t offA = (uint32_t)((wm * 64 + (lane & 15)) * 72 + (lane >> 4) * 8) << 1;
    const uint32_t offB = SBH_OFF +
        ((uint32_t)((wn * 32 + (lane & 7) + ((lane >> 4) << 3)) * 72 + ((lane >> 3) & 1) * 8) << 1);
    const uint32_t B_LO = SBL_DELTA, MF = 2304;

    ld_stage(sb, A, lda, Bh, Bl, ldb, rowBase, colBase, 0, Nrows, tid, dual, kw16);
    CP_COMMIT();

    for (int kt = 0; kt < Ktiles; kt++) {
        uint32_t stb = sb + (uint32_t)(kt & 1) * STG;
        if (kt + 1 < Ktiles) {
            ld_stage(sb + (uint32_t)((kt + 1) & 1) * STG, A, lda, Bh, Bl, ldb,
                     rowBase, colBase, (kt + 1) * 64, Nrows, tid, dual, kw16);
            CP_COMMIT();
            CP_WAIT1();
        } else {
            CP_WAIT0();
        }
        __syncthreads();

        uint32_t aA = stb + offA;
        uint32_t aB = stb + offB;
        for (int ks = 0; ks < ksteps; ks++) {
            uint32_t kso = ks * 32;
            uint32_t bh[4][2], bl[4][2];
            LDSM4(bh[0][0], bh[0][1], bh[1][0], bh[1][1], aB + kso);
            LDSM4(bh[2][0], bh[2][1], bh[3][0], bh[3][1], aB + MF + kso);
            if (dual) {
                LDSM4(bl[0][0], bl[0][1], bl[1][0], bl[1][1], aB + B_LO + kso);
                LDSM4(bl[2][0], bl[2][1], bl[3][0], bl[3][1], aB + B_LO + MF + kso);
            }
#pragma unroll
            for (int mf = 0; mf < 4; mf++) {
                uint32_t ar[4];
                LDSM4(ar[0], ar[1], ar[2], ar[3], aA + mf * MF + kso);
#pragma unroll
                for (int nf = 0; nf < 4; nf++) {
                    mma16(acc[mf][nf], ar, bh[nf]);
                    if (dual) mma16(acc[mf][nf], ar, bl[nf]);
                }
            }
        }
        __syncthreads();
    }

    int gid = lane >> 2, tig = lane & 3;
    if (mode == 2) {
#pragma unroll
        for (int mf = 0; mf < 4; mf++) {
#pragma unroll
            for (int half = 0; half < 2; half++) {
                int r = rowBase + wm * 64 + mf * 16 + gid + half * 8;
                if (r >= Nrows) continue;
#pragma unroll
                for (int nf = 0; nf < 4; nf++) {
                    int c0 = colBase + wn * 32 + nf * 8 + tig * 2;
                    float v0 = acc[mf][nf][half * 2];
                    float v1 = acc[mf][nf][half * 2 + 1];
                    float o0 = 0.f, o1 = 0.f;
                    if (c0 < HID)
                        o0 = fmaxf(fmaf(v0 + bias[c0], scale[c0], shift[c0]), 0.f);
                    if (c0 + 1 < HID)
                        o1 = fmaxf(fmaf(v1 + bias[c0 + 1], scale[c0 + 1], shift[c0 + 1]), 0.f);
                    *(__half2*)(O + (size_t)r * LDAH + c0) =
                        __halves2half2(__float2half_rn(o0), __float2half_rn(o1));
                }
            }
        }
    } else {
        unsigned* spool = (unsigned*)smch;
        int g0 = batch[rowBase];
        int rlast = min(rowBase + 255, Nrows - 1);
        int range = batch[rlast] - g0 + 1;
        for (int i = tid; i < range * 64; i += 256) spool[i] = 0x007FFFFFu;
        __syncthreads();
#pragma unroll
        for (int mf = 0; mf < 4; mf++) {
#pragma unroll
            for (int half = 0; half < 2; half++) {
                int r = rowBase + wm * 64 + mf * 16 + gid + half * 8;
                if (r >= Nrows) continue;
                int bloc = (batch[r] - g0) * 64;
#pragma unroll
                for (int nf = 0; nf < 4; nf++) {
                    int c0 = colBase + wn * 32 + nf * 8 + tig * 2;
                    float v0 = acc[mf][nf][half * 2];
                    float v1 = acc[mf][nf][half * 2 + 1];
                    int cl = wn * 32 + nf * 8 + tig * 2;
                    if (c0 < HID)
                        atomicMax(&spool[bloc + cl], enc_f(v0 + bias[c0]));
                    if (c0 + 1 < HID)
                        atomicMax(&spool[bloc + cl + 1], enc_f(v1 + bias[c0 + 1]));
                }
            }
        }
        __syncthreads();
        for (int i = tid; i < range * 64; i += 256) {
            int bgr = i >> 6;
            int c = colBase + (i & 63);
            if (c < HID)
                atomicMax(&pool[(g0 + bgr) * HID + c], spool[i]);
        }
    }
}

// fp16 aggregation: z[n] = dn * sum_e w_e * h[src_e] + dn^2 * h[n]   (half2 lanes)
__global__ void k_agg16(const __half* __restrict__ src, int N) {
    int n = blockIdx.x;
    int c0 = threadIdx.x * 2;
    int s0 = g_offs[n], s1 = g_offs[n + 1];
    float a0 = 0.f, a1 = 0.f;
    int e = s0;
    for (; e + 4 <= s1; e += 4) {
        int2 e0 = g_csr[e],     e1 = g_csr[e + 1];
        int2 e2 = g_csr[e + 2], e3 = g_csr[e + 3];
        float2 p0 = __half22float2(*(const __half2*)(src + (size_t)e0.x * LDAH + c0));
        float2 p1 = __half22float2(*(const __half2*)(src + (size_t)e1.x * LDAH + c0));
        float2 p2 = __half22float2(*(const __half2*)(src + (size_t)e2.x * LDAH + c0));
        float2 p3 = __half22float2(*(const __half2*)(src + (size_t)e3.x * LDAH + c0));
        float w0 = __int_as_float(e0.y), w1 = __int_as_float(e1.y);
        float w2 = __int_as_float(e2.y), w3 = __int_as_float(e3.y);
        a0 += w0 * p0.x + w1 * p1.x + w2 * p2.x + w3 * p3.x;
        a1 += w0 * p0.y + w1 * p1.y + w2 * p2.y + w3 * p3.y;
    }
    for (; e < s1; ++e) {
        int2 ed = g_csr[e];
        float w = __int_as_float(ed.y);
        float2 p = __half22float2(*(const __half2*)(src + (size_t)ed.x * LDAH + c0));
        a0 += w * p.x;
        a1 += w * p.y;
    }
    float dn = g_dis[n];
    float2 self = __half22float2(*(const __half2*)(src + (size_t)n * LDAH + c0));
    float v0 = dn * a0 + dn * dn * self.x;
    float v1 = dn * a1 + dn * dn * self.y;
    *(__half2*)(g_Z + (size_t)n * LDZ + c0) = __floats2half2_rn(v0, v1);
}

__global__ void k_finalize(const float* __restrict__ Wout,
                           const float* __restrict__ bout,
                           float* __restrict__ out, int G) {
    int g = blockIdx.x, t = threadIdx.x;
    __shared__ float red[256];
    float p = 0.f;
    for (int c = t; c < HID; c += 256)
        p += dec_f(g_pool[g * HID + c]) * Wout[c];
    red[t] = p;
    __syncthreads();
    for (int o = 128; o; o >>= 1) {
        if (t < o) red[t] += red[t + o];
        __syncthreads();
    }
    if (t == 0) out[g] = red[0] + bout[0];
}

// ---------------- host launcher ----------------
extern "C" void kernel_launch(void* const* d_in, const int* in_sizes, int n_in,
                              void* d_out, int out_size) {
    const float* x     = (const float*)d_in[0];
    const int*   ei    = (const int*)  d_in[1];
    const int*   batch = (const int*)  d_in[2];
    const float* W0    = (const float*)d_in[3];
    const float* b0    = (const float*)d_in[4];
    const float* W_h   = (const float*)d_in[5];
    const float* b_h   = (const float*)d_in[6];
    const float* bn_g  = (const float*)d_in[7];
    const float* bn_b  = (const float*)d_in[8];
    const float* bn_m  = (const float*)d_in[9];
    const float* bn_v  = (const float*)d_in[10];
    const float* W_jk  = (const float*)d_in[11];
    const float* b_jk  = (const float*)d_in[12];
    const float* W_out = (const float*)d_in[13];
    const float* b_out = (const float*)d_in[14];
    float* out = (float*)d_out;

    int N = in_sizes[0] / INCH;
    int E = in_sizes[1] / 2;
    int G = out_size;
    int SB = (N + 255) / 256;
    int EB = (E + 255) / 256;
    int poolBlks = (G * HID + 255) / 256;

    cudaFuncSetAttribute(k_mma, cudaFuncAttributeMaxDynamicSharedMemorySize, SMEM_BYTES);

    __half *a0, *axs, *zz, *w0h, *w0l, *whh, *wjh;
    cudaGetSymbolAddress((void**)&a0,  g_A0);
    cudaGetSymbolAddress((void**)&axs, g_Axs);
    cudaGetSymbolAddress((void**)&zz,  g_Z);
    cudaGetSymbolAddress((void**)&w0h, g_W0th);
    cudaGetSymbolAddress((void**)&w0l, g_W0tl);
    cudaGetSymbolAddress((void**)&whh, g_Whth);
    cudaGetSymbolAddress((void**)&wjh, g_Wjkth);
    float *bns, *bnh;
    cudaGetSymbolAddress((void**)&bns, g_bnscale);
    cudaGetSymbolAddress((void**)&bnh, g_bnshift);
    unsigned* pool;
    cudaGetSymbolAddress((void**)&pool, g_pool);

    k_prep<<<EB + 1023 + poolBlks, 256>>>(ei, E, EB, W0, W_h, W_jk,
                                          bn_g, bn_b, bn_m, bn_v, G);
    k_scan_blk<<<SB, 256>>>(N);
    k_scan_add<<<SB, 256>>>(N, SB);
    k_fill<<<(E + 255) / 256, 256>>>(ei, E);
    k_aggregate_x<<<(N * 32 + 255) / 256, 256>>>(x, N);

    dim3 grid(3, (N + 255) / 256);   // 294 CTAs -> single wave at 2 CTAs/SM

    // layer 0: (Âx)@W0 -> bias+bn0+relu -> fp16 concat cols [0,192)  (16-wide K)
    k_mma<<<grid, 256, SMEM_BYTES>>>(a0, 16, w0h, w0l, 16, N, 1,
                                     axs, b0, bns, bnh,
                                     (const int*)0, (unsigned*)0, 2, 1, 1, 1);
    // hidden layers 1..3
    for (int i = 1; i <= 3; i++) {
        k_agg16<<<N, 96>>>(axs + (size_t)(i - 1) * 192, N);
        k_mma<<<grid, 256, SMEM_BYTES>>>(zz, LDZ,
                                         whh + (size_t)(i - 1) * 36864,
                                         whh + (size_t)(i - 1) * 36864, 192,
                                         N, 3,
                                         axs + (size_t)i * 192,
                                         b_h + (size_t)(i - 1) * HID,
                                         bns + i * HID, bnh + i * HID,
                                         (const int*)0, (unsigned*)0, 2, 0, 4, 0);
    }
    // JK GEMM fused with smem-staged max-pool
    k_mma<<<grid, 256, SMEM_BYTES>>>(axs, LDAH, wjh, wjh, 768, N, 12,
                                     (__half*)0,
                                     b_jk, (const float*)0, (const float*)0,
                                     batch, pool, 3, 0, 4, 0);

    k_finalize<<<G, 256>>>(W_out, b_out, out, G);
}